// round 7
// baseline (speedup 1.0000x reference)
#include <cuda_runtime.h>
#include <cuda_bf16.h>

#define NXv 432
#define NYv 496
#define NZv 1
#define CAPV (NXv * NYv * NZv)      // 214272
#define MAXP 100
#define NPTS_MAX 300000
#define NB_SCAN ((CAPV + 1023) / 1024)   // 210

// ---- scratch (static device globals; no allocation allowed) ----
__device__ int g_count[CAPV];
__device__ int g_count2[CAPV];
__device__ int g_voxid[CAPV];
__device__ int g_base[CAPV];
__device__ int g_lin[NPTS_MAX];
__device__ int g_tmpidx[NPTS_MAX];
__device__ int g_blkOcc[256];
__device__ int g_blkPts[256];

// ---------------------------------------------------------------
// K0: zero per-voxel counters
__global__ void k_init() {
    int i = blockIdx.x * blockDim.x + threadIdx.x;
    if (i < CAPV) { g_count[i] = 0; g_count2[i] = 0; }
}

// K_fill: fill exactly n4 float4s of output: 0 everywhere, -1 in [cS4, cE4)
__global__ void k_fill(float4* __restrict__ out, int n4, int cS4, int cE4) {
    int i = blockIdx.x * blockDim.x + threadIdx.x;
    if (i >= n4) return;
    float v = (i >= cS4 && i < cE4) ? -1.0f : 0.0f;
    out[i] = make_float4(v, v, v, v);
}

// K1: per-point voxel binning + per-voxel counting.
// BINNING NUMERICS: emulate XLA's algebraic rewrite of x/const ->
// x * reciprocal(const). fp32(1/fp32(0.16)) rounds to exactly 6.25f, and
// fp32(1/fp32(4.0)) = 0.25f. Using RN multiply by these reciprocals matches
// the executed JAX reference; a true RN divide disagrees by ~1 ulp on a
// handful of points, flipping their voxel and shifting ~14% of the compacted
// rows (the measured rel_err 0.5267 signature).
__global__ void k_bin(const float4* __restrict__ pts, int n) {
    int i = blockIdx.x * blockDim.x + threadIdx.x;
    if (i >= n) return;
    float4 p = pts[i];
    bool valid = (p.x >= 0.0f)    && (p.x < 69.12f) &&
                 (p.y >= -39.68f) && (p.y < 39.68f) &&
                 (p.z >= -3.0f)   && (p.z < 1.0f);
    int lin = CAPV;
    if (valid) {
        float qx = __fmul_rn(__fsub_rn(p.x,   0.0f),  6.25f);
        float qy = __fmul_rn(__fsub_rn(p.y, -39.68f), 6.25f);
        float qz = __fmul_rn(__fsub_rn(p.z,  -3.0f),  0.25f);
        int vx = (int)floorf(qx);
        int vy = (int)floorf(qy);
        int vz = (int)floorf(qz);
        vx = min(max(vx, 0), NXv - 1);
        vy = min(max(vy, 0), NYv - 1);
        vz = min(max(vz, 0), NZv - 1);
        lin = (vz * NYv + vy) * NXv + vx;
        atomicAdd(&g_count[lin], 1);
    }
    g_lin[i] = lin;
}

// K2: per-block scans of (occupied flag, capped count). 256 thr x 4 elem = 1024/block
__global__ void k_scan1() {
    __shared__ int sO[256], sP[256];
    int b = blockIdx.x, t = threadIdx.x;
    int e0 = b * 1024 + t * 4;
    int occ[4], cap[4];
    int so = 0, sp = 0;
#pragma unroll
    for (int j = 0; j < 4; j++) {
        int e = e0 + j;
        int c = (e < CAPV) ? g_count[e] : 0;
        occ[j] = (c > 0) ? 1 : 0;
        cap[j] = (c < MAXP) ? c : MAXP;
        so += occ[j]; sp += cap[j];
    }
    sO[t] = so; sP[t] = sp;
    __syncthreads();
    for (int off = 1; off < 256; off <<= 1) {
        int vo = 0, vp = 0;
        if (t >= off) { vo = sO[t - off]; vp = sP[t - off]; }
        __syncthreads();
        sO[t] += vo; sP[t] += vp;
        __syncthreads();
    }
    int exO = sO[t] - so, exP = sP[t] - sp;
#pragma unroll
    for (int j = 0; j < 4; j++) {
        int e = e0 + j;
        if (e < CAPV) { g_voxid[e] = exO; g_base[e] = exP; }
        exO += occ[j]; exP += cap[j];
    }
    if (t == 255) { g_blkOcc[b] = sO[255]; g_blkPts[b] = sP[255]; }
}

// K3: exclusive scan of the 210 block totals (single block)
__global__ void k_scan2() {
    __shared__ int sO[256], sP[256];
    int t = threadIdx.x;
    int vo = (t < NB_SCAN) ? g_blkOcc[t] : 0;
    int vp = (t < NB_SCAN) ? g_blkPts[t] : 0;
    sO[t] = vo; sP[t] = vp;
    __syncthreads();
    for (int off = 1; off < 256; off <<= 1) {
        int ao = 0, ap = 0;
        if (t >= off) { ao = sO[t - off]; ap = sP[t - off]; }
        __syncthreads();
        sO[t] += ao; sP[t] += ap;
        __syncthreads();
    }
    if (t < NB_SCAN) { g_blkOcc[t] = sO[t] - vo; g_blkPts[t] = sP[t] - vp; }
}

// K4: finalize voxid/base with block offsets; write coords + counts for occupied.
// coords per the listed reference decode: z = lin/(NY*NX), y = rem/NX, x = rem%NX.
__global__ void k_final(float* __restrict__ coords_out, float* __restrict__ counts_out,
                        int hasCoords, int hasCounts) {
    int e = blockIdx.x * blockDim.x + threadIdx.x;
    if (e >= CAPV) return;
    int b = e >> 10;
    int vox = g_voxid[e] + g_blkOcc[b];
    int bas = g_base[e] + g_blkPts[b];
    g_voxid[e] = vox;
    g_base[e]  = bas;
    int c = g_count[e];
    if (c > 0) {
        int z   = e / (NYv * NXv);
        int rem = e % (NYv * NXv);
        int y   = rem / NXv;
        int x   = rem % NXv;
        if (hasCoords) {
            coords_out[(size_t)vox * 3 + 0] = (float)z;
            coords_out[(size_t)vox * 3 + 1] = (float)y;
            coords_out[(size_t)vox * 3 + 2] = (float)x;
        }
        if (hasCounts) {
            counts_out[vox] = (float)c;   // uncapped, matches segment_sum
        }
    }
}

// K5: scatter point indices into compact per-voxel slots
__global__ void k_scatter(int n) {
    int i = blockIdx.x * blockDim.x + threadIdx.x;
    if (i >= n) return;
    int lin = g_lin[i];
    if (lin >= CAPV) return;
    int slot = atomicAdd(&g_count2[lin], 1);
    if (slot < MAXP) {
        int pos = g_base[lin] + slot;
        if (pos < NPTS_MAX) g_tmpidx[pos] = i;
    }
}

// K6: per occupied voxel — sort slot indices (restores original point order,
// i.e. the reference's stable sort), gather features, write rows
__global__ void k_write(const float4* __restrict__ pts, float4* __restrict__ vox_out) {
    int e = blockIdx.x * blockDim.x + threadIdx.x;
    if (e >= CAPV) return;
    int c = g_count[e];
    if (c == 0) return;
    int cc = (c < MAXP) ? c : MAXP;
    int vox = g_voxid[e];
    int bas = g_base[e];
    // insertion sort of cc indices (cc is tiny: lambda ~1.2 pts/voxel)
    for (int i = 1; i < cc; i++) {
        int key = g_tmpidx[bas + i];
        int j = i - 1;
        while (j >= 0 && g_tmpidx[bas + j] > key) {
            g_tmpidx[bas + j + 1] = g_tmpidx[bas + j];
            j--;
        }
        g_tmpidx[bas + j + 1] = key;
    }
    size_t rowBase = (size_t)vox * MAXP;
    for (int j = 0; j < cc; j++) {
        int p = g_tmpidx[bas + j];
        vox_out[rowBase + j] = pts[p];
    }
}

extern "C" void kernel_launch(void* const* d_in, const int* in_sizes, int n_in,
                              void* d_out, int out_size) {
    const float4* pts = (const float4*)d_in[0];
    int n = in_sizes[0] / 4;          // 300000 points, 4 floats each
    if (n > NPTS_MAX) n = NPTS_MAX;
    float* out = (float*)d_out;

    const long long voxFloats   = (long long)CAPV * MAXP * 4;  // 85,708,800
    const long long coordFloats = (long long)CAPV * 3;         // 642,816
    const long long total = (long long)out_size;

    // Only touch slices the buffer actually contains; never write past out_size.
    const int hasCoords = (total >= voxFloats + coordFloats) ? 1 : 0;
    const int hasCounts = (total >= voxFloats + coordFloats + CAPV) ? 1 : 0;

    const int n4  = (int)(total / 4);
    const int cS4 = hasCoords ? (int)(voxFloats / 4) : n4;
    const int cE4 = hasCoords ? (int)((voxFloats + coordFloats) / 4) : n4;

    float* coords_out = out + voxFloats;
    float* counts_out = out + voxFloats + coordFloats;

    const int T = 256;
    k_init<<<(CAPV + T - 1) / T, T>>>();
    k_fill<<<(n4 + T - 1) / T, T>>>((float4*)d_out, n4, cS4, cE4);
    k_bin<<<(n + T - 1) / T, T>>>(pts, n);
    k_scan1<<<NB_SCAN, 256>>>();
    k_scan2<<<1, 256>>>();
    k_final<<<(CAPV + T - 1) / T, T>>>(coords_out, counts_out, hasCoords, hasCounts);
    k_scatter<<<(n + T - 1) / T, T>>>(n);
    k_write<<<(CAPV + T - 1) / T, T>>>(pts, (float4*)d_out);
}